// round 17
// baseline (speedup 1.0000x reference)
#include <cuda_runtime.h>
#include <cuda_fp16.h>
#include <cuda_bf16.h>
#include <cstdint>
#include <cstddef>

#define BB  8
#define NN  4096
#define KK  32
#define CC  64
#define CIN 67
#define NCELL 216   // 6x6x6

// -------- scratch (no allocation allowed -> __device__ globals) --------
__device__ __align__(16) __half g_G[(size_t)BB*NN*128]; // merged fp16 [b][j][0:64]=GA, [64:128]=G1
__device__ __align__(16) float g_F0[(size_t)BB*NN*CC]; // attention output (pre-residual), [b, n, c]
__device__ int   g_idx[(size_t)BB*NN*KK];              // ball-query neighbor indices
__device__ __align__(16) float4 g_sp4[(size_t)BB*NN];  // cell-sorted points (x,y,z,|p|^2)
__device__ int   g_sidx[(size_t)BB*NN];                // original index of sorted points
__device__ int   g_cellstart[BB][NCELL+8];             // cell range starts (+ total sentinel)
__device__ __align__(16) float g_wD3[3*128];           // [d][u]: u<64 -> w_attn[u][d], else w1[u-64][d]
__device__ __align__(16) uint32_t g_bfH[2048];         // w2 hi-bf16 B-fragments [kt][nt][lane][2]
__device__ __align__(16) uint32_t g_bfL[2048];         // w2 lo-bf16 residual fragments
__device__ __align__(16) float g_wf1T[CC*CC];          // wf1 transposed [cp][c]
__device__ __align__(16) float g_wf2T[CC*CC];          // wf2 transposed [cp][c]

// ---------------- helpers ----------------
__device__ __forceinline__ uint32_t smem_u32(const void* p_) {
    uint32_t a;
    asm("{ .reg .u64 t; cvta.to.shared.u64 t, %1; cvt.u32.u64 %0, t; }" : "=r"(a) : "l"(p_));
    return a;
}
__device__ __forceinline__ void ldsm_x4(uint32_t* r, uint32_t addr) {
    asm volatile("ldmatrix.sync.aligned.m8n8.x4.shared.b16 {%0,%1,%2,%3}, [%4];"
        : "=r"(r[0]), "=r"(r[1]), "=r"(r[2]), "=r"(r[3]) : "r"(addr));
}
__device__ __forceinline__ void mma_bf16(float* d, const uint32_t* a, uint32_t b0, uint32_t b1) {
    asm volatile("mma.sync.aligned.m16n8k16.row.col.f32.bf16.bf16.f32 "
        "{%0,%1,%2,%3}, {%4,%5,%6,%7}, {%8,%9}, {%0,%1,%2,%3};"
        : "+f"(d[0]), "+f"(d[1]), "+f"(d[2]), "+f"(d[3])
        : "r"(a[0]), "r"(a[1]), "r"(a[2]), "r"(a[3]), "r"(b0), "r"(b1));
}
__device__ __forceinline__ unsigned long long pack2(float lo, float hi) {
    unsigned long long r;
    asm("mov.b64 %0, {%1, %2};" : "=l"(r) : "f"(lo), "f"(hi));
    return r;
}
__device__ __forceinline__ float2 unpack2(unsigned long long v) {
    float2 r;
    asm("mov.b64 {%0, %1}, %2;" : "=f"(r.x), "=f"(r.y) : "l"(v));
    return r;
}
__device__ __forceinline__ void fma2(unsigned long long &acc, unsigned long long a, unsigned long long b) {
    asm("fma.rn.f32x2 %0, %1, %2, %3;" : "=l"(acc) : "l"(a), "l"(b), "l"(acc));
}
__device__ __forceinline__ int cell_coord(float x) {
    int c = (int)(x * 6.0f);
    return c > 5 ? 5 : c;
}

// ================== launch A: grid-build | p-copy | prep (small, fast) ==================
#define PREA_SMEM 49152

__global__ void __launch_bounds__(512) prep_build(
        const float* __restrict__ p,
        const float* __restrict__ w_attn, const float* __restrict__ w1,
        const float* __restrict__ w2,
        const float* __restrict__ wf1, const float* __restrict__ wf2,
        float* __restrict__ out) {
    extern __shared__ float sm[];
    int blk = blockIdx.x;
    int tid = threadIdx.x;

    if (blk < 8) {
        // ---------- build: counting-sort points into 6x6x6 cells ----------
        int b = blk;
        int* s_cell = reinterpret_cast<int*>(sm);
        int* s_cnt  = s_cell + NN;
        int* s_ofs  = s_cnt + NCELL;
        for (int i = tid; i < NCELL; i += 512) s_cnt[i] = 0;
        __syncthreads();

        const float* pb = p + (size_t)b*NN*3;
        for (int jj = tid; jj < NN; jj += 512) {
            float x = pb[jj*3+0], y = pb[jj*3+1], z = pb[jj*3+2];
            int cell = (cell_coord(z)*6 + cell_coord(y))*6 + cell_coord(x);
            s_cell[jj] = cell;
            atomicAdd(&s_cnt[cell], 1);
        }
        __syncthreads();
        if (tid == 0) {
            int run = 0;
            for (int i = 0; i < NCELL; i++) {
                g_cellstart[b][i] = run;
                s_ofs[i] = run;
                run += s_cnt[i];
            }
            g_cellstart[b][NCELL] = run;
        }
        __syncthreads();
        for (int jj = tid; jj < NN; jj += 512) {
            int cell = s_cell[jj];
            int pos = atomicAdd(&s_ofs[cell], 1);
            float x = pb[jj*3+0], y = pb[jj*3+1], z = pb[jj*3+2];
            float sq = __fadd_rn(__fadd_rn(__fmul_rn(x,x), __fmul_rn(y,y)), __fmul_rn(z,z));
            g_sp4[(size_t)b*NN + pos] = make_float4(x, y, z, sq);
            g_sidx[(size_t)b*NN + pos] = jj;
        }

    } else if (blk < 40) {
        // ---------- p passthrough copy into out[0 : B*N*3) ----------
        int cb = blk - 8;
        const float4* src = reinterpret_cast<const float4*>(p);
        float4* dst = reinterpret_cast<float4*>(out);
        int lo = cb*768, hi = lo + 768;
        for (int i = lo + tid; i < hi; i += 512) dst[i] = src[i];

    } else {
        // ---------- prep: weight repack ----------
        for (int i = tid; i < 3*128; i += 512) {
            int d = i / 128, u = i % 128;
            g_wD3[i] = (u < 64) ? w_attn[u*CIN + d] : w1[(u-64)*CIN + d];
        }
        for (int i = tid; i < 2048; i += 512) {
            int r    = i & 1;
            int lane = (i >> 1) & 31;
            int nt   = (i >> 6) & 7;
            int kt   = i >> 9;
            int k0 = kt*16 + (lane & 3)*2 + r*8;
            int n  = nt*8 + (lane >> 2);
            float v0 = w2[n*64 + k0], v1 = w2[n*64 + k0 + 1];
            __nv_bfloat16 h0 = __float2bfloat16(v0), h1 = __float2bfloat16(v1);
            __nv_bfloat162 hi2; hi2.x = h0; hi2.y = h1;
            __nv_bfloat162 lo2;
            lo2.x = __float2bfloat16(v0 - __bfloat162float(h0));
            lo2.y = __float2bfloat16(v1 - __bfloat162float(h1));
            g_bfH[i] = *reinterpret_cast<uint32_t*>(&hi2);
            g_bfL[i] = *reinterpret_cast<uint32_t*>(&lo2);
        }
        for (int i = tid; i < CC*CC; i += 512) {
            int c = i / CC, cp = i % CC;
            g_wf1T[cp*CC + c] = wf1[i];
            g_wf2T[cp*CC + c] = wf2[i];
        }
    }
}

// ================== launch B: bq | ga fused (mutually independent -> overlap) ==================
#define PREB_SMEM 49152

__global__ void __launch_bounds__(512) bq_ga_kernel(
        const float* __restrict__ p, const float* __restrict__ f,
        const float* __restrict__ w_attn, const float* __restrict__ b_attn,
        const float* __restrict__ w1, const float* __restrict__ b1) {
    extern __shared__ float sm[];
    int blk = blockIdx.x;
    int tid = threadIdx.x;

    if (blk < 512) {
        // ---------- bq: grid-accelerated ball query ----------
        int (*s_hit)[130] = reinterpret_cast<int(*)[130]>(sm);

        int bb = blk;
        int b = bb >> 6;
        int nbase = (bb & 63) << 6;
        int wi = tid >> 5, lane = tid & 31;
        const float r2 = (float)(0.15*0.15);
        unsigned lmask = (1u << lane) - 1u;
        const float4* sp4 = g_sp4 + (size_t)b*NN;
        const int* sidx = g_sidx + (size_t)b*NN;
        const int* cs = &g_cellstart[b][0];

#pragma unroll 1
        for (int qq = 0; qq < 4; qq++) {
            int n = nbase + wi*4 + qq;
            const float* pn = p + ((size_t)b*NN + n)*3;
            float x = pn[0], y = pn[1], z = pn[2];
            float sq = __fadd_rn(__fadd_rn(__fmul_rn(x,x), __fmul_rn(y,y)), __fmul_rn(z,z));
            float ax = -2.0f*x, ay = -2.0f*y, az = -2.0f*z;
            int cx = cell_coord(x), cy = cell_coord(y), cz = cell_coord(z);
            int x0 = max(cx-1, 0), x1 = min(cx+1, 5);
            int y0 = max(cy-1, 0), y1 = min(cy+1, 5);
            int z0 = max(cz-1, 0), z1 = min(cz+1, 5);

            int hcnt = 0;
#pragma unroll 1
            for (int dz = z0; dz <= z1; dz++) {
#pragma unroll 1
                for (int dy = y0; dy <= y1; dy++) {
                    int rowb = (dz*6 + dy)*6;
                    int start = __ldg(&cs[rowb + x0]);
                    int end   = __ldg(&cs[rowb + x1 + 1]);
#pragma unroll 1
                    for (int base2 = start; base2 < end; base2 += 32) {
                        int pos = base2 + lane;
                        bool inr = pos < end;
                        float4 sp = make_float4(0.f, 0.f, 0.f, 1e9f);
                        if (inr) sp = __ldg(&sp4[pos]);
                        float d2 = fmaf(ax, sp.x, fmaf(ay, sp.y, fmaf(az, sp.z, sq + sp.w)));
                        bool within = inr && (d2 <= r2);
                        unsigned m = __ballot_sync(0xffffffffu, within);
                        int pr = hcnt + __popc(m & lmask);
                        if (within && pr < 128) s_hit[wi][pr] = __ldg(&sidx[pos]);
                        hcnt += __popc(m);
                    }
                }
            }
            if (hcnt > 128) hcnt = 128;
            __syncwarp();

            int h0 = (lane        < hcnt) ? s_hit[wi][lane]      : 0x7FFFFFFF;
            int h1 = (lane + 32   < hcnt) ? s_hit[wi][lane + 32] : 0x7FFFFFFF;
            int h2 = (lane + 64   < hcnt) ? s_hit[wi][lane + 64] : 0x7FFFFFFF;
            int h3 = (lane + 96   < hcnt) ? s_hit[wi][lane + 96] : 0x7FFFFFFF;

            int v;
            if (hcnt <= 32) {
                int mn = h0;
#pragma unroll
                for (int off = 16; off > 0; off >>= 1)
                    mn = min(mn, __shfl_xor_sync(0xffffffffu, mn, off));
                v = (lane < hcnt) ? h0 : mn;
            } else {
                int lo = 0, hi = 4095;
                while (lo < hi) {
                    int mid = (lo + hi) >> 1;
                    int c = __popc(__ballot_sync(0xffffffffu, h0 <= mid))
                          + __popc(__ballot_sync(0xffffffffu, h1 <= mid))
                          + __popc(__ballot_sync(0xffffffffu, h2 <= mid))
                          + __popc(__ballot_sync(0xffffffffu, h3 <= mid));
                    if (c >= 32) hi = mid; else lo = mid + 1;
                }
                int T = lo;
                __syncwarp();
                int bc = 0;
#pragma unroll
                for (int i = 0; i < 4; i++) {
                    int hv = (i == 0) ? h0 : (i == 1) ? h1 : (i == 2) ? h2 : h3;
                    bool sel = hv <= T;
                    unsigned m = __ballot_sync(0xffffffffu, sel);
                    int ppos = bc + __popc(m & lmask);
                    if (sel) s_hit[wi][ppos] = hv;
                    bc += __popc(m);
                }
                __syncwarp();
                v = s_hit[wi][lane];
            }

            // bitonic sort ascending -> deterministic order
#pragma unroll
            for (int kk2 = 2; kk2 <= 32; kk2 <<= 1) {
#pragma unroll
                for (int jx = kk2 >> 1; jx > 0; jx >>= 1) {
                    int partner = __shfl_xor_sync(0xffffffffu, v, jx);
                    bool up = ((lane & kk2) == 0);
                    bool smallh = ((lane & jx) == 0);
                    int mn = min(v, partner), mx = max(v, partner);
                    v = (smallh == up) ? mn : mx;
                }
            }
            g_idx[((size_t)b*NN + n)*KK + lane] = v;
            __syncwarp();
        }

    } else {
        // ---------- ga: GA/G1 precompute -> merged fp16 g_G rows ----------
        float* s_f  = sm;
        float* s_wa = sm + 4096;
        float* s_w1 = sm + 8192;
        int gb = blk - 512;
        int b  = gb >> 6;
        int j0 = (gb & 63) << 6;

        for (int lin = tid; lin < 64*64; lin += 512) {
            int i = lin >> 6, c = lin & 63;
            s_wa[i*64 + c] = w_attn[c*CIN + 3 + i];
            s_w1[i*64 + c] = w1[c*CIN + 3 + i];
        }
        for (int lin = tid; lin < 64*64; lin += 512) {
            int i = lin >> 6, jj = lin & 63;
            s_f[i*64 + jj] = f[((size_t)b*CC + i)*NN + j0 + jj];
        }
        __syncthreads();

        int j  = tid & 63;
        int c0 = (tid >> 6) << 3;
        unsigned long long accA2[4], acc12[4];
#pragma unroll
        for (int q = 0; q < 4; q++) {
            accA2[q] = pack2(__ldg(&b_attn[c0+2*q]), __ldg(&b_attn[c0+2*q+1]));
            acc12[q] = pack2(__ldg(&b1[c0+2*q]),     __ldg(&b1[c0+2*q+1]));
        }

#pragma unroll 4
        for (int i = 0; i < 64; i++) {
            float fv = s_f[i*64 + j];
            unsigned long long fv2 = pack2(fv, fv);
            const ulonglong2* wa = reinterpret_cast<const ulonglong2*>(&s_wa[i*64 + c0]);
            const ulonglong2* wb = reinterpret_cast<const ulonglong2*>(&s_w1[i*64 + c0]);
            ulonglong2 A0 = wa[0], A1 = wa[1];
            ulonglong2 B0 = wb[0], B1 = wb[1];
            fma2(accA2[0], A0.x, fv2); fma2(accA2[1], A0.y, fv2);
            fma2(accA2[2], A1.x, fv2); fma2(accA2[3], A1.y, fv2);
            fma2(acc12[0], B0.x, fv2); fma2(acc12[1], B0.y, fv2);
            fma2(acc12[2], B1.x, fv2); fma2(acc12[3], B1.y, fv2);
        }
        size_t base = ((size_t)b*NN + j0 + j)*128 + c0;
        {
            float2 a0 = unpack2(accA2[0]), a1 = unpack2(accA2[1]);
            float2 a2 = unpack2(accA2[2]), a3 = unpack2(accA2[3]);
            union { __half2 h[4]; uint4 u4; } ca;
            ca.h[0] = __floats2half2_rn(a0.x, a0.y);
            ca.h[1] = __floats2half2_rn(a1.x, a1.y);
            ca.h[2] = __floats2half2_rn(a2.x, a2.y);
            ca.h[3] = __floats2half2_rn(a3.x, a3.y);
            *reinterpret_cast<uint4*>(&g_G[base]) = ca.u4;
            float2 o0 = unpack2(acc12[0]), o1 = unpack2(acc12[1]);
            float2 o2 = unpack2(acc12[2]), o3 = unpack2(acc12[3]);
            union { __half2 h[4]; uint4 u4; } cb;
            cb.h[0] = __floats2half2_rn(o0.x, o0.y);
            cb.h[1] = __floats2half2_rn(o1.x, o1.y);
            cb.h[2] = __floats2half2_rn(o2.x, o2.y);
            cb.h[3] = __floats2half2_rn(o3.x, o3.y);
            *reinterpret_cast<uint4*>(&g_G[base + 64]) = cb.u4;
        }
    }
}

// ---------------- fused main: mma.sync GEMM, 4 points/block, 3 blocks/SM ----------------
#define SMM_RHI  0
#define SMM_RLO  18432
#define SMM_E    36864
#define SMM_META 55296
#define SM_MAIN  59392

__global__ void __launch_bounds__(256, 3) main_kernel(const float* __restrict__ p,
        const float* __restrict__ b2) {
    extern __shared__ char smc[];
    uint32_t smem_base = smem_u32(smc);
    float4* s_meta = reinterpret_cast<float4*>(smc + SMM_META);

    int tid  = threadIdx.x;
    int w    = tid >> 5;
    int lane = tid & 31;
    int pbase = blockIdx.x * 4;

    if (w < 4) {
        int pid = pbase + w;
        int b = pid >> 12, n = pid & 4095;
        int j = g_idx[(size_t)pid*KK + lane];
        const float* pn = p + ((size_t)b*NN + n)*3;
        const float* pj = p + ((size_t)b*NN + j)*3;
        float4 m;
        m.x = pj[0] - pn[0];
        m.y = pj[1] - pn[1];
        m.z = pj[2] - pn[2];
        m.w = __int_as_float(j);
        s_meta[w*32 + lane] = m;
    }
    __syncthreads();

    // ---- phase 1 (warp-specialized): warps 0-3 -> R(pt=w), warps 4-7 -> E(pt=w-4) ----
    {
        bool isR = (w < 4);
        int pt = w & 3;
        int pid = pbase + pt;
        int b = pid >> 12;
        int lh  = lane >> 4;
        int u16 = (lane & 15) * 4;
        int u   = isR ? (64 + u16) : u16;
        float4 wx = *reinterpret_cast<const float4*>(&g_wD3[0*128 + u]);
        float4 wy = *reinterpret_cast<const float4*>(&g_wD3[1*128 + u]);
        float4 wz = *reinterpret_cast<const float4*>(&g_wD3[2*128 + u]);
        __half* Ep = reinterpret_cast<__half*>(smc + SMM_E) + pt*2304;
        const __half* Gb = g_G + (size_t)b*NN*128;

#pragma unroll 8
        for (int kk = 0; kk < 16; kk++) {
            int k = kk*2 + lh;
            float4 m = s_meta[pt*32 + k];
            int j = __float_as_int(m.w);
            uint2 gv = __ldg(reinterpret_cast<const uint2*>(&Gb[(size_t)j*128 + u]));
            float2 g01 = __half22float2(*reinterpret_cast<__half2*>(&gv.x));
            float2 g23 = __half22float2(*reinterpret_cast<__half2*>(&gv.y));
            float4 v;
            v.x = g01.x + wx.x*m.x + wy.x*m.y + wz.x*m.z;
            v.y = g01.y + wx.y*m.x + wy.y*m.y + wz.y*m.z;
            v.z = g23.x + wx.z*m.x + wy.z*m.y + wz.z*m.z;
            v.w = g23.y + wx.w*m.x + wy.w*m.y + wz.w*m.z;
            if (isR) {
                float r0 = fmaxf(v.x, 0.0f), r1 = fmaxf(v.y, 0.0f);
                float r2v = fmaxf(v.z, 0.0f), r3 = fmaxf(v.w, 0.0f);
                __nv_bfloat16 h0 = __float2bfloat16(r0), h1 = __float2bfloat16(r1);
                __nv_bfloat16 h2 = __float2bfloat16(r2v), h3 = __float2bfloat16(r3);
                __nv_bfloat162 hp0; hp0.x = h0; hp0.y = h1;
                __nv_bfloat162 hp1; hp1.x = h2; hp1.y = h3;
                __nv_bfloat162 lp0; lp0.x = __float2bfloat16(r0 - __bfloat162float(h0));
                                    lp0.y = __float2bfloat16(r1 - __bfloat162float(h1));
                __nv_bfloat162 lp1; lp1.x = __float2bfloat16(r2v - __bfloat162float(h2));
                                    lp1.y = __float2bfloat16(r3 - __bfloat162float(h3));
                int row = pt*32 + k;
                uint32_t roff = (uint32_t)(row*72 + u16)*2;
                *reinterpret_cast<uint2*>(smc + SMM_RHI + roff) =
                    make_uint2(*reinterpret_cast<uint32_t*>(&hp0), *reinterpret_cast<uint32_t*>(&hp1));
                *reinterpret_cast<uint2*>(smc + SMM_RLO + roff) =
                    make_uint2(*reinterpret_cast<uint32_t*>(&lp0), *reinterpret_cast<uint32_t*>(&lp1));
            } else {
                union { __half2 h[2]; uint2 u2; } cv;
                cv.h[0] = __floats2half2_rn(__expf(v.x), __expf(v.y));
                cv.h[1] = __floats2half2_rn(__expf(v.z), __expf(v.w));
                *reinterpret_cast<uint2*>(&Ep[k*72 + u16]) = cv.u2;
            }
        }
    }
    __syncthreads();

    // ---- mma GEMM + softmax-weighted epilogue: warp = (pt = w&3, mh = w>>2) ----
    {
        int pt = w & 3;
        int mh = w >> 2;

        int r8 = lane & 7, mmat = lane >> 3;
        int arow = pt*32 + mh*16 + r8 + ((mmat & 1) << 3);
        uint32_t acolB = (uint32_t)(((mmat >> 1) << 3) * 2);
        uint32_t abase = smem_base + (uint32_t)(arow * 144) + acolB;

        float acc[8][4];
#pragma unroll
        for (int nt = 0; nt < 8; nt++)
#pragma unroll
            for (int q = 0; q < 4; q++) acc[nt][q] = 0.0f;

#pragma unroll
        for (int kt = 0; kt < 4; kt++) {
            uint32_t ah[4], al[4];
            ldsm_x4(ah, abase + SMM_RHI + kt*32);
            ldsm_x4(al, abase + SMM_RLO + kt*32);
#pragma unroll
            for (int nt = 0; nt < 8; nt++) {
                int bidx = ((kt*8 + nt)*32 + lane)*2;
                uint2 bh = __ldg(reinterpret_cast<const uint2*>(&g_bfH[bidx]));
                uint2 bl = __ldg(reinterpret_cast<const uint2*>(&g_bfL[bidx]));
                mma_bf16(acc[nt], ah, bh.x, bh.y);
                mma_bf16(acc[nt], al, bh.x, bh.y);
                mma_bf16(acc[nt], ah, bl.x, bl.y);
            }
        }

        const __half* Eb = reinterpret_cast<const __half*>(smc + SMM_E);
        float* red = reinterpret_cast<float*>(smc + SMM_META);
        int r0 = mh*16 + (lane >> 2);
        int c00 = (lane & 3) * 2;
#pragma unroll
        for (int nt = 0; nt < 8; nt++) {
            int c0 = nt*8 + c00;
            float2 e0 = __half22float2(*reinterpret_cast<const __half2*>(&Eb[pt*2304 + r0*72 + c0]));
            float2 e1 = __half22float2(*reinterpret_cast<const __half2*>(&Eb[pt*2304 + (r0+8)*72 + c0]));
            float v0 = e0.x*acc[nt][0] + e1.x*acc[nt][2];
            float v1 = e0.y*acc[nt][1] + e1.y*acc[nt][3];
            float v2 = e0.x + e1.x;
            float v3 = e0.y + e1.y;
            bool up4 = (lane & 4) != 0;
            float s0 = up4 ? v0 : v2;
            float s1 = up4 ? v1 : v3;
            float rA = __shfl_xor_sync(0xffffffffu, s0, 4);
            float rB = __shfl_xor_sync(0xffffffffu, s1, 4);
            v0 = (up4 ? v2 : v0) + rA;
            v1 = (up4 ? v3 : v1) + rB;
            bool up8 = (lane & 8) != 0;
            float s2 = up8 ? v0 : v1;
            float rC = __shfl_xor_sync(0xffffffffu, s2, 8);
            v0 = (up8 ? v1 : v0) + rC;
            v0 += __shfl_xor_sync(0xffffffffu, v0, 16);
            if (lane < 16) {
                int c = nt*8 + (lane & 3)*2 + ((lane >> 3) & 1);
                int d = (lane >> 2) & 1;
                red[((mh*4 + pt)*64 + c)*2 + d] = v0;
            }
        }
    }
    __syncthreads();

    {
        int pt = tid >> 6, c = tid & 63;
        const float* red = reinterpret_cast<const float*>(smc + SMM_META);
        float num = red[(pt*64 + c)*2 + 0] + red[((4 + pt)*64 + c)*2 + 0];
        float den = red[(pt*64 + c)*2 + 1] + red[((4 + pt)*64 + c)*2 + 1];
        g_F0[(size_t)(pbase + pt)*CC + c] = num / den + __ldg(&b2[c]);
    }
}

// ---------------- tail: relu(F0+f) -> 2x (64x64) MLP -> relu residual ----------------
__global__ void __launch_bounds__(256) tail_kernel(const float* __restrict__ f,
        const float* __restrict__ bf1, const float* __restrict__ bf2,
        float* __restrict__ outF) {
    __shared__ float s_F1[64*68];
    __shared__ float s_H[64*68];

    int b   = blockIdx.x >> 6;
    int n0g = (blockIdx.x & 63) << 6;
    int tid = threadIdx.x;

    {
        int c = tid >> 2, q = tid & 3;
        const float* frow = f + ((size_t)b*CC + c)*NN + n0g;
        const float* f0b  = g_F0 + ((size_t)b*NN + n0g)*CC + c;
#pragma unroll
        for (int i = 0; i < 4; i++) {
            int nn = q*16 + i*4;
            float4 fv = *reinterpret_cast<const float4*>(frow + nn);
            float a0 = __ldg(&f0b[(nn+0)*CC]);
            float a1 = __ldg(&f0b[(nn+1)*CC]);
            float a2 = __ldg(&f0b[(nn+2)*CC]);
            float a3 = __ldg(&f0b[(nn+3)*CC]);
            float4 r;
            r.x = fmaxf(a0 + fv.x, 0.0f);
            r.y = fmaxf(a1 + fv.y, 0.0f);
            r.z = fmaxf(a2 + fv.z, 0.0f);
            r.w = fmaxf(a3 + fv.w, 0.0f);
            *reinterpret_cast<float4*>(&s_F1[c*68 + nn]) = r;
        }
    }
    __syncthreads();

    int ct = (tid >> 4) << 2;
    int nt = (tid & 15) << 2;

    {
        float acc[16];
#pragma unroll
        for (int r = 0; r < 4; r++) {
            float bv = __ldg(&bf1[ct+r]);
#pragma unroll
            for (int jj = 0; jj < 4; jj++) acc[r*4+jj] = bv;
        }
#pragma unroll 4
        for (int cp = 0; cp < 64; cp++) {
            float4 wv = __ldg(reinterpret_cast<const float4*>(&g_wf1T[cp*64 + ct]));
            float4 fv = *reinterpret_cast<const float4*>(&s_F1[cp*68 + nt]);
            acc[0]  += wv.x*fv.x; acc[1]  += wv.x*fv.y; acc[2]  += wv.x*fv.z; acc[3]  += wv.x*fv.w;
            acc[4]  += wv.y*fv.x; acc[5]  += wv.y*fv.y; acc[6]  += wv.y*fv.z; acc[7]  += wv.y*fv.w;
            acc[8]  += wv.z*fv.x; acc[9]  += wv.z*fv.y; acc[10] += wv.z*fv.z; acc[11] += wv.z*fv.w;
            acc[12] += wv.w*fv.x; acc[13] += wv.w*fv.y; acc[14] += wv.w*fv.z; acc[15] += wv.w*fv.w;
        }
#pragma unroll
        for (int r = 0; r < 4; r++) {
            float4 o;
            o.x = fmaxf(acc[r*4+0], 0.0f);
            o.y = fmaxf(acc[r*4+1], 0.0f);
            o.z = fmaxf(acc[r*4+2], 0.0f);
            o.w = fmaxf(acc[r*4+3], 0.0f);
            *reinterpret_cast<float4*>(&s_H[(ct+r)*68 + nt]) = o;
        }
    }
    __syncthreads();

    {
        float acc[16];
#pragma unroll
        for (int r = 0; r < 4; r++) {
            float bv = __ldg(&bf2[ct+r]);
#pragma unroll
            for (int jj = 0; jj < 4; jj++) acc[r*4+jj] = bv;
        }
#pragma unroll 4
        for (int cp = 0; cp < 64; cp++) {
            float4 wv = __ldg(reinterpret_cast<const float4*>(&g_wf2T[cp*64 + ct]));
            float4 hv = *reinterpret_cast<const float4*>(&s_H[cp*68 + nt]);
            acc[0]  += wv.x*hv.x; acc[1]  += wv.x*hv.y; acc[2]  += wv.x*hv.z; acc[3]  += wv.x*hv.w;
            acc[4]  += wv.y*hv.x; acc[5]  += wv.y*hv.y; acc[6]  += wv.y*hv.z; acc[7]  += wv.y*hv.w;
            acc[8]  += wv.z*hv.x; acc[9]  += wv.z*hv.y; acc[10] += wv.z*hv.z; acc[11] += wv.z*hv.w;
            acc[12] += wv.w*hv.x; acc[13] += wv.w*hv.y; acc[14] += wv.w*hv.z; acc[15] += wv.w*hv.w;
        }
#pragma unroll
        for (int r = 0; r < 4; r++) {
            const float* idn = &s_F1[(ct+r)*68 + nt];
            float4 o;
            o.x = fmaxf(acc[r*4+0] + idn[0], 0.0f);
            o.y = fmaxf(acc[r*4+1] + idn[1], 0.0f);
            o.z = fmaxf(acc[r*4+2] + idn[2], 0.0f);
            o.w = fmaxf(acc[r*4+3] + idn[3], 0.0f);
            *reinterpret_cast<float4*>(&outF[((size_t)b*CC + ct + r)*NN + n0g + nt]) = o;
        }
    }
}

// ---------------- launch ----------------
extern "C" void kernel_launch(void* const* d_in, const int* in_sizes, int n_in,
                              void* d_out, int out_size) {
    const float* p      = (const float*)d_in[0];
    const float* f      = (const float*)d_in[1];
    const float* w_attn = (const float*)d_in[2];
    const float* b_attn = (const float*)d_in[3];
    const float* w1     = (const float*)d_in[4];
    const float* b1     = (const float*)d_in[5];
    const float* w2     = (const float*)d_in[6];
    const float* b2     = (const float*)d_in[7];
    const float* wf1    = (const float*)d_in[8];
    const float* bf1    = (const float*)d_in[9];
    const float* wf2    = (const float*)d_in[10];
    const float* bf2    = (const float*)d_in[11];
    float* out = (float*)d_out;

    cudaFuncSetAttribute(prep_build, cudaFuncAttributeMaxDynamicSharedMemorySize, PREA_SMEM);
    prep_build<<<41, 512, PREA_SMEM>>>(p, w_attn, w1, w2, wf1, wf2, out);

    cudaFuncSetAttribute(bq_ga_kernel, cudaFuncAttributeMaxDynamicSharedMemorySize, PREB_SMEM);
    bq_ga_kernel<<<1024, 512, PREB_SMEM>>>(p, f, w_attn, b_attn, w1, b1);

    cudaFuncSetAttribute(main_kernel, cudaFuncAttributeMaxDynamicSharedMemorySize, SM_MAIN);
    main_kernel<<<BB*NN/4, 256, SM_MAIN>>>(p, b2);

    tail_kernel<<<BB*(NN/64), 256>>>(f, bf1, bf2, out + (size_t)BB*NN*3);
}